// round 1
// baseline (speedup 1.0000x reference)
#include <cuda_runtime.h>
#include <math.h>

// Problem sizes
#define BD   512          // batch
#define DD   2048         // dim
#define NTOT (BD*DD)      // 1,048,576 elements
#define NV   (NTOT/4)     // float4 count

#define MAX_STEPS 32
#define TOLC      0.01f
#define SPEED_TOL 1e-3f
#define DT0       0.1f
#define MIN_DT    0.1f

// ---------------- device state (no allocations allowed) ----------------
__device__ float g_X [NTOT];   // current x
__device__ float g_XS[NTOT];   // stage input x + dt*sum(a*k)
__device__ float g_YS[NTOT];   // r(XS)
__device__ float g_X5[NTOT];   // candidate 5th-order solution
__device__ float g_K [6][NTOT];
__device__ float g_dt;
__device__ int   g_done;
__device__ int   g_step;
__device__ unsigned int g_err_bits;  // atomicMax of |x5-x4| (non-negative float bits)
__device__ unsigned int g_spd_bits;  // atomicMax of |x5-x|

// ---------------- helpers ----------------
__device__ __forceinline__ float reflect_f(float x) {
    int i = (int)x;                 // trunc toward zero == jnp astype(int32)
    return ((i & 1) == 0) ? x : 1.0f - x;
}
__device__ __forceinline__ void axpy4(float4& x, float c, const float4 k) {
    x.x += c * k.x; x.y += c * k.y; x.z += c * k.z; x.w += c * k.w;
}

// ---------------- init ----------------
__global__ void k_init(const float* __restrict__ x0) {
    for (int i = blockIdx.x * blockDim.x + threadIdx.x; i < NV;
         i += gridDim.x * blockDim.x)
        ((float4*)g_X)[i] = ((const float4*)x0)[i];
    if (blockIdx.x == 0 && threadIdx.x == 0) {
        g_dt = DT0; g_done = 0; g_step = 0; g_err_bits = 0u; g_spd_bits = 0u;
    }
}

// ---------------- stage prep: XS = X + dt*sum a_i K_i ; YS = r(XS) ----------------
template <int NK>
__global__ void k_stage(float a0, float a1, float a2, float a3, float a4) {
    if (g_done) return;
    float dt = g_dt;
    const float4* X4  = (const float4*)g_X;
    float4*       XS4 = (float4*)g_XS;
    float4*       YS4 = (float4*)g_YS;
    for (int i = blockIdx.x * blockDim.x + threadIdx.x; i < NV;
         i += gridDim.x * blockDim.x) {
        float4 xs = X4[i];
        if (NK >= 1) axpy4(xs, dt * a0, ((const float4*)g_K[0])[i]);
        if (NK >= 2) axpy4(xs, dt * a1, ((const float4*)g_K[1])[i]);
        if (NK >= 3) axpy4(xs, dt * a2, ((const float4*)g_K[2])[i]);
        if (NK >= 4) axpy4(xs, dt * a3, ((const float4*)g_K[3])[i]);
        if (NK >= 5) axpy4(xs, dt * a4, ((const float4*)g_K[4])[i]);
        float4 ys;
        ys.x = reflect_f(xs.x); ys.y = reflect_f(xs.y);
        ys.z = reflect_f(xs.z); ys.w = reflect_f(xs.w);
        XS4[i] = xs; YS4[i] = ys;
    }
}

// ---------------- GEMM + pvf epilogue: K[kidx] = s(XS) * (YS @ W + b) ----------------
#define BM 64
#define BN 64
#define BK 16

__global__ __launch_bounds__(256)
void k_gemm_pvf(const float* __restrict__ W, const float* __restrict__ bias, int kidx) {
    if (g_done) return;
    __shared__ float As[BK][BM + 4];   // padded stride to spread banks
    __shared__ float Bs[BK][BN];

    const int bm = blockIdx.y * BM;
    const int bn = blockIdx.x * BN;
    const int tid = threadIdx.x;
    const int tx = tid & 15;       // 0..15 -> 4 cols each
    const int ty = tid >> 4;       // 0..15 -> 4 rows each

    // A-tile load: 64 rows x 16 k  (one float4 per thread)
    const int arow = tid >> 2;            // 0..63
    const int acol = (tid & 3) << 2;      // 0,4,8,12
    // B-tile load: 16 rows x 64 n  (one float4 per thread)
    const int brow = tid >> 4;            // 0..15
    const int bcol = (tid & 15) << 2;     // 0..60

    const float* Aptr = g_YS + (bm + arow) * DD + acol;
    const float* Bptr = W + brow * DD + bn + bcol;

    float acc[4][4];
#pragma unroll
    for (int i = 0; i < 4; i++)
#pragma unroll
        for (int j = 0; j < 4; j++) acc[i][j] = 0.0f;

    for (int k0 = 0; k0 < DD; k0 += BK) {
        float4 av = *(const float4*)(Aptr + k0);
        float4 bv = *(const float4*)(Bptr + (size_t)k0 * DD);
        As[acol + 0][arow] = av.x;
        As[acol + 1][arow] = av.y;
        As[acol + 2][arow] = av.z;
        As[acol + 3][arow] = av.w;
        *(float4*)&Bs[brow][bcol] = bv;
        __syncthreads();
#pragma unroll
        for (int k = 0; k < BK; k++) {
            float4 a = *(const float4*)&As[k][ty << 2];
            float4 b = *(const float4*)&Bs[k][tx << 2];
            acc[0][0] += a.x * b.x; acc[0][1] += a.x * b.y; acc[0][2] += a.x * b.z; acc[0][3] += a.x * b.w;
            acc[1][0] += a.y * b.x; acc[1][1] += a.y * b.y; acc[1][2] += a.y * b.z; acc[1][3] += a.y * b.w;
            acc[2][0] += a.z * b.x; acc[2][1] += a.z * b.y; acc[2][2] += a.z * b.z; acc[2][3] += a.z * b.w;
            acc[3][0] += a.w * b.x; acc[3][1] += a.w * b.y; acc[3][2] += a.w * b.z; acc[3][3] += a.w * b.w;
        }
        __syncthreads();
    }

    float* Kout = g_K[kidx];
    const int ncol = bn + (tx << 2);
    float4 bv = *(const float4*)&bias[ncol];
#pragma unroll
    for (int i = 0; i < 4; i++) {
        int m = bm + (ty << 2) + i;
        float4 xsv = *(const float4*)&g_XS[(size_t)m * DD + ncol];
        float4 r;
        float v0 = acc[i][0] + bv.x;
        float v1 = acc[i][1] + bv.y;
        float v2 = acc[i][2] + bv.z;
        float v3 = acc[i][3] + bv.w;
        r.x = (((int)xsv.x & 1) == 0) ? v0 : -v0;
        r.y = (((int)xsv.y & 1) == 0) ? v1 : -v1;
        r.z = (((int)xsv.z & 1) == 0) ? v2 : -v2;
        r.w = (((int)xsv.w & 1) == 0) ? v3 : -v3;
        *(float4*)&Kout[(size_t)m * DD + ncol] = r;
    }
}

// ---------------- combine: x5, x4, err/speed reduction ----------------
__global__ void k_combine() {
    if (g_done) return;
    const float dt = g_dt;
    // RKF coefficients (5th- and 4th-order solutions)
    const float B1 = (float)(16.0 / 135.0);
    const float B3 = (float)(6656.0 / 12825.0);
    const float B4 = (float)(28561.0 / 56430.0);
    const float B5 = (float)(-9.0 / 50.0);
    const float B6 = (float)(2.0 / 55.0);
    const float C1 = (float)(25.0 / 216.0);
    const float C3 = (float)(1408.0 / 2565.0);
    const float C4 = (float)(2197.0 / 4104.0);
    const float C5 = (float)(-1.0 / 5.0);

    float emax = 0.0f, smax = 0.0f;
    const float4* X4  = (const float4*)g_X;
    const float4* K1  = (const float4*)g_K[0];
    const float4* K3  = (const float4*)g_K[2];
    const float4* K4  = (const float4*)g_K[3];
    const float4* K5  = (const float4*)g_K[4];
    const float4* K6  = (const float4*)g_K[5];
    float4* X54 = (float4*)g_X5;

    for (int i = blockIdx.x * blockDim.x + threadIdx.x; i < NV;
         i += gridDim.x * blockDim.x) {
        float4 x  = X4[i];
        float4 k1 = K1[i], k3 = K3[i], k4 = K4[i], k5 = K5[i], k6 = K6[i];
        float x5[4], x4v[4], xx[4] = {x.x, x.y, x.z, x.w};
        float kk1[4] = {k1.x, k1.y, k1.z, k1.w};
        float kk3[4] = {k3.x, k3.y, k3.z, k3.w};
        float kk4[4] = {k4.x, k4.y, k4.z, k4.w};
        float kk5[4] = {k5.x, k5.y, k5.z, k5.w};
        float kk6[4] = {k6.x, k6.y, k6.z, k6.w};
#pragma unroll
        for (int c = 0; c < 4; c++) {
            float s5 = B1 * kk1[c] + B3 * kk3[c] + B4 * kk4[c] + B5 * kk5[c] + B6 * kk6[c];
            float s4 = C1 * kk1[c] + C3 * kk3[c] + C4 * kk4[c] + C5 * kk5[c];
            x5[c]  = xx[c] + dt * s5;
            x4v[c] = xx[c] + dt * s4;
            emax = fmaxf(emax, fabsf(x5[c] - x4v[c]));
            smax = fmaxf(smax, fabsf(x5[c] - xx[c]));
        }
        float4 o; o.x = x5[0]; o.y = x5[1]; o.z = x5[2]; o.w = x5[3];
        X54[i] = o;
    }
#pragma unroll
    for (int o = 16; o > 0; o >>= 1) {
        emax = fmaxf(emax, __shfl_xor_sync(0xffffffffu, emax, o));
        smax = fmaxf(smax, __shfl_xor_sync(0xffffffffu, smax, o));
    }
    if ((threadIdx.x & 31) == 0) {
        atomicMax(&g_err_bits, __float_as_uint(emax));
        atomicMax(&g_spd_bits, __float_as_uint(smax));
    }
}

// ---------------- controller (1 thread) ----------------
__global__ void k_decide() {
    if (g_done) { g_step = 0; return; }
    float err = __uint_as_float(g_err_bits);
    float spd = __uint_as_float(g_spd_bits);
    float dt  = g_dt;
    int accept = (err < TOLC) ? 1 : 0;
    g_step = accept;
    if (accept && (spd / dt) < SPEED_TOL) g_done = 1;
    float scale = 0.9f * powf(TOLC / (err + 1e-12f), 0.2f);
    scale = fminf(fmaxf(scale, 0.1f), 4.0f);
    g_dt = fmaxf(dt * scale, MIN_DT);
    g_err_bits = 0u; g_spd_bits = 0u;
}

// ---------------- accept update: X = X5 ----------------
__global__ void k_update() {
    if (!g_step) return;
    for (int i = blockIdx.x * blockDim.x + threadIdx.x; i < NV;
         i += gridDim.x * blockDim.x)
        ((float4*)g_X)[i] = ((const float4*)g_X5)[i];
}

// ---------------- output ----------------
__global__ void k_final(float* __restrict__ out) {
    for (int i = blockIdx.x * blockDim.x + threadIdx.x; i < NV;
         i += gridDim.x * blockDim.x)
        ((float4*)out)[i] = ((const float4*)g_X)[i];
}

// ---------------- launch ----------------
extern "C" void kernel_launch(void* const* d_in, const int* in_sizes, int n_in,
                              void* d_out, int out_size) {
    const float* x0   = (const float*)d_in[0];
    const float* W    = (const float*)d_in[1];
    const float* bias = (const float*)d_in[2];
    float* out = (float*)d_out;

    const int EW_GRID = 512, EW_BLK = 256;
    dim3 ggrid(DD / BN, BD / BM);  // (32, 8)

    k_init<<<EW_GRID, EW_BLK>>>(x0);

    for (int step = 0; step < MAX_STEPS; step++) {
        // k1
        k_stage<0><<<EW_GRID, EW_BLK>>>(0.f, 0.f, 0.f, 0.f, 0.f);
        k_gemm_pvf<<<ggrid, 256>>>(W, bias, 0);
        // k2
        k_stage<1><<<EW_GRID, EW_BLK>>>(0.25f, 0.f, 0.f, 0.f, 0.f);
        k_gemm_pvf<<<ggrid, 256>>>(W, bias, 1);
        // k3
        k_stage<2><<<EW_GRID, EW_BLK>>>((float)(3.0 / 32.0), (float)(9.0 / 32.0),
                                        0.f, 0.f, 0.f);
        k_gemm_pvf<<<ggrid, 256>>>(W, bias, 2);
        // k4
        k_stage<3><<<EW_GRID, EW_BLK>>>((float)(1932.0 / 2197.0),
                                        (float)(-7200.0 / 2197.0),
                                        (float)(7296.0 / 2197.0), 0.f, 0.f);
        k_gemm_pvf<<<ggrid, 256>>>(W, bias, 3);
        // k5
        k_stage<4><<<EW_GRID, EW_BLK>>>((float)(439.0 / 216.0), -8.0f,
                                        (float)(3680.0 / 513.0),
                                        (float)(-845.0 / 4104.0), 0.f);
        k_gemm_pvf<<<ggrid, 256>>>(W, bias, 4);
        // k6
        k_stage<5><<<EW_GRID, EW_BLK>>>((float)(-8.0 / 27.0), 2.0f,
                                        (float)(-3544.0 / 2565.0),
                                        (float)(1859.0 / 4104.0),
                                        (float)(-11.0 / 40.0));
        k_gemm_pvf<<<ggrid, 256>>>(W, bias, 5);

        k_combine<<<EW_GRID, EW_BLK>>>();
        k_decide<<<1, 1>>>();
        k_update<<<EW_GRID, EW_BLK>>>();
    }

    k_final<<<EW_GRID, EW_BLK>>>(out);
}

// round 3
// speedup vs baseline: 2.3238x; 2.3238x over previous
#include <cuda_runtime.h>
#include <cuda_bf16.h>
#include <cstdint>
#include <math.h>

// ---------------- problem sizes ----------------
#define BD   512
#define DD   2048
#define NTOT (BD*DD)
#define NV   (NTOT/4)
#define WTOT (DD*DD)
#define WV   (WTOT/4)

#define MAX_STEPS 32
#define TOLC      0.01f
#define SPEED_TOL 1e-3f
#define DT0       0.1f
#define MIN_DT    0.1f

// ---------------- device state ----------------
__device__ float g_X [NTOT];
__device__ float g_XS[NTOT];
__device__ float g_X5[NTOT];
__device__ __nv_bfloat16 g_Ah[NTOT];
__device__ __nv_bfloat16 g_Al[NTOT];
__device__ __nv_bfloat16 g_Wh[WTOT];
__device__ __nv_bfloat16 g_Wl[WTOT];
__device__ float g_K [6][NTOT];
__device__ float g_dt;
__device__ int   g_done;
__device__ int   g_step;
__device__ unsigned int g_err_bits;
__device__ unsigned int g_spd_bits;

// ---------------- helpers ----------------
__device__ __forceinline__ float reflect_f(float x) {
    int i = (int)x;
    return ((i & 1) == 0) ? x : 1.0f - x;
}
__device__ __forceinline__ void axpy4(float4& x, float c, const float4 k) {
    x.x += c * k.x; x.y += c * k.y; x.z += c * k.z; x.w += c * k.w;
}
__device__ __forceinline__ uint32_t smem_u32(const void* p) {
    uint32_t a;
    asm("{ .reg .u64 t; cvta.to.shared.u64 t, %1; cvt.u32.u64 %0, t; }" : "=r"(a) : "l"(p));
    return a;
}
__device__ __forceinline__ void cp16(uint32_t dst, const void* src) {
    asm volatile("cp.async.cg.shared.global [%0], [%1], 16;" :: "r"(dst), "l"(src));
}
__device__ __forceinline__ void cp_commit() { asm volatile("cp.async.commit_group;" ::: "memory"); }
template <int N> __device__ __forceinline__ void cp_wait() {
    asm volatile("cp.async.wait_group %0;" :: "n"(N) : "memory");
}
__device__ __forceinline__ void ldsm4(uint32_t* r, uint32_t addr) {
    asm volatile("ldmatrix.sync.aligned.m8n8.x4.shared.b16 {%0,%1,%2,%3}, [%4];"
                 : "=r"(r[0]), "=r"(r[1]), "=r"(r[2]), "=r"(r[3]) : "r"(addr));
}
__device__ __forceinline__ void mma16816(float* c, const uint32_t* a, const uint32_t* b) {
    asm("mma.sync.aligned.m16n8k16.row.col.f32.bf16.bf16.f32 "
        "{%0,%1,%2,%3}, {%4,%5,%6,%7}, {%8,%9}, {%0,%1,%2,%3};"
        : "+f"(c[0]), "+f"(c[1]), "+f"(c[2]), "+f"(c[3])
        : "r"(a[0]), "r"(a[1]), "r"(a[2]), "r"(a[3]), "r"(b[0]), "r"(b[1]));
}

// ---------------- init / split ----------------
__global__ void k_splitW(const float* __restrict__ W) {
    for (int i = blockIdx.x * blockDim.x + threadIdx.x; i < WV; i += gridDim.x * blockDim.x) {
        float4 w = ((const float4*)W)[i];
        __nv_bfloat16 h[4], l[4];
        float v[4] = {w.x, w.y, w.z, w.w};
#pragma unroll
        for (int c = 0; c < 4; c++) {
            h[c] = __float2bfloat16_rn(v[c]);
            l[c] = __float2bfloat16_rn(v[c] - __bfloat162float(h[c]));
        }
        *(uint2*)&g_Wh[i * 4] = *(uint2*)h;
        *(uint2*)&g_Wl[i * 4] = *(uint2*)l;
    }
}

__global__ void k_init(const float* __restrict__ x0) {
    for (int i = blockIdx.x * blockDim.x + threadIdx.x; i < NV; i += gridDim.x * blockDim.x)
        ((float4*)g_X)[i] = ((const float4*)x0)[i];
    if (blockIdx.x == 0 && threadIdx.x == 0) {
        g_dt = DT0; g_done = 0; g_step = 0; g_err_bits = 0u; g_spd_bits = 0u;
    }
}

// ---------------- stage prep: XS = X + dt*sum a_i K_i ; split r(XS) to bf16 ----------------
template <int NK>
__global__ void k_stage(float a0, float a1, float a2, float a3, float a4) {
    if (g_done) return;
    float dt = g_dt;
    for (int i = blockIdx.x * blockDim.x + threadIdx.x; i < NV; i += gridDim.x * blockDim.x) {
        float4 xs = ((const float4*)g_X)[i];
        if (NK >= 1) axpy4(xs, dt * a0, ((const float4*)g_K[0])[i]);
        if (NK >= 2) axpy4(xs, dt * a1, ((const float4*)g_K[1])[i]);
        if (NK >= 3) axpy4(xs, dt * a2, ((const float4*)g_K[2])[i]);
        if (NK >= 4) axpy4(xs, dt * a3, ((const float4*)g_K[3])[i]);
        if (NK >= 5) axpy4(xs, dt * a4, ((const float4*)g_K[4])[i]);
        float v[4] = {xs.x, xs.y, xs.z, xs.w};
        __nv_bfloat16 h[4], l[4];
#pragma unroll
        for (int c = 0; c < 4; c++) {
            float y = reflect_f(v[c]);
            h[c] = __float2bfloat16_rn(y);
            l[c] = __float2bfloat16_rn(y - __bfloat162float(h[c]));
        }
        ((float4*)g_XS)[i] = xs;
        *(uint2*)&g_Ah[i * 4] = *(uint2*)h;
        *(uint2*)&g_Al[i * 4] = *(uint2*)l;
    }
}

// ---------------- mma.sync GEMM: K[kidx] = sign(XS) * (r(XS) @ W + b) ----------------
// bf16x3: Ah*Wh + Ah*Wl + Al*Wh, fp32 accum. Tile 128x64x32, 4-stage cp.async.
#define BMT 128
#define BNT 64
#define BKC 32
#define NITER (DD / BKC)       // 64
#define PITCH 80               // 64B data + 16B pad -> conflict-free ldmatrix
#define AH_OFF 0
#define AL_OFF (128 * PITCH)                 // 10240
#define BH_OFF (2 * 128 * PITCH)             // 20480
#define BL_OFF (2 * 128 * PITCH + 64 * PITCH)// 25600
#define STAGE  (2 * 128 * PITCH + 2 * 64 * PITCH)  // 30720
#define GEMM_SMEM (4 * STAGE)  // 122880

__device__ __forceinline__ void load_stage(uint32_t sbase, int k0, int bm, int bn, int tid) {
#pragma unroll
    for (int i = 0; i < 2; i++) {
        int ch = tid + i * 256;          // 512 chunks: 128 rows x 4
        int r = ch >> 2, c = ch & 3;
        uint32_t off = (uint32_t)(r * PITCH + c * 16);
        size_t go = (size_t)(bm + r) * DD + k0 + c * 8;
        cp16(sbase + AH_OFF + off, g_Ah + go);
        cp16(sbase + AL_OFF + off, g_Al + go);
    }
    {
        int r = tid >> 2, c = tid & 3;   // 256 chunks: 64 rows x 4
        uint32_t off = (uint32_t)(r * PITCH + c * 16);
        size_t go = (size_t)(bn + r) * DD + k0 + c * 8;
        cp16(sbase + BH_OFF + off, g_Wh + go);
        cp16(sbase + BL_OFF + off, g_Wl + go);
    }
    cp_commit();
}

__global__ __launch_bounds__(256, 1)
void k_gemm_pvf(const float* __restrict__ bias, int kidx) {
    if (g_done) return;
    extern __shared__ char smem[];
    uint32_t sb = smem_u32(smem);
    const int tid  = threadIdx.x;
    const int wid  = tid >> 5;
    const int lane = tid & 31;
    const int wm   = wid >> 1;      // 0..3 -> m offset 32 each
    const int wn   = wid & 1;       // 0..1 -> n offset 32 each
    const int bm   = blockIdx.y * BMT;
    const int bn   = blockIdx.x * BNT;

    float acc[2][4][4];
#pragma unroll
    for (int i = 0; i < 2; i++)
#pragma unroll
        for (int j = 0; j < 4; j++)
#pragma unroll
            for (int c = 0; c < 4; c++) acc[i][j][c] = 0.0f;

    load_stage(sb + 0 * STAGE, 0 * BKC, bm, bn, tid);
    load_stage(sb + 1 * STAGE, 1 * BKC, bm, bn, tid);
    load_stage(sb + 2 * STAGE, 2 * BKC, bm, bn, tid);

    const int g  = lane >> 3;
    const int l7 = lane & 7;

    for (int it = 0; it < NITER; ++it) {
        if (it <= NITER - 3)      cp_wait<2>();
        else if (it == NITER - 2) cp_wait<1>();
        else                      cp_wait<0>();
        __syncthreads();

        uint32_t stg = sb + (uint32_t)((it & 3) * STAGE);
#pragma unroll
        for (int ks = 0; ks < 2; ks++) {
            uint32_t ah[2][4], al[2][4], bh[2][4], bl[2][4];
#pragma unroll
            for (int mt = 0; mt < 2; mt++) {
                int row = wm * 32 + mt * 16 + ((g & 1) << 3) + l7;
                int chunk = (ks << 1) + (g >> 1);
                uint32_t off = (uint32_t)(row * PITCH + chunk * 16);
                ldsm4(ah[mt], stg + AH_OFF + off);
                ldsm4(al[mt], stg + AL_OFF + off);
            }
#pragma unroll
            for (int np = 0; np < 2; np++) {
                int n = wn * 32 + np * 16 + ((g >> 1) << 3) + l7;
                int chunk = (ks << 1) + (g & 1);
                uint32_t off = (uint32_t)(n * PITCH + chunk * 16);
                ldsm4(bh[np], stg + BH_OFF + off);
                ldsm4(bl[np], stg + BL_OFF + off);
            }
#pragma unroll
            for (int mt = 0; mt < 2; mt++)
#pragma unroll
                for (int nt = 0; nt < 4; nt++) {
                    const uint32_t* bhp = &bh[nt >> 1][(nt & 1) * 2];
                    const uint32_t* blp = &bl[nt >> 1][(nt & 1) * 2];
                    mma16816(acc[mt][nt], ah[mt], bhp);
                    mma16816(acc[mt][nt], ah[mt], blp);
                    mma16816(acc[mt][nt], al[mt], bhp);
                }
        }
        __syncthreads();

        int J = it + 3;
        if (J < NITER) load_stage(sb + (uint32_t)((J & 3) * STAGE), J * BKC, bm, bn, tid);
    }

    // epilogue
    float* Kout = g_K[kidx];
    const int m_base = bm + wm * 32;
    const int n_base = bn + wn * 32;
#pragma unroll
    for (int mt = 0; mt < 2; mt++)
#pragma unroll
        for (int nt = 0; nt < 4; nt++) {
            int m0 = m_base + mt * 16 + (lane >> 2);
            int n0 = n_base + nt * 8 + 2 * (lane & 3);
            float2 bv = *(const float2*)&bias[n0];
#pragma unroll
            for (int half = 0; half < 2; half++) {
                int m = m0 + half * 8;
                float2 xs = *(const float2*)&g_XS[(size_t)m * DD + n0];
                float v0 = acc[mt][nt][half * 2 + 0] + bv.x;
                float v1 = acc[mt][nt][half * 2 + 1] + bv.y;
                float2 o;
                o.x = (((int)xs.x & 1) == 0) ? v0 : -v0;
                o.y = (((int)xs.y & 1) == 0) ? v1 : -v1;
                *(float2*)&Kout[(size_t)m * DD + n0] = o;
            }
        }
}

// ---------------- combine / decide / update / final ----------------
__global__ void k_combine() {
    if (g_done) return;
    const float dt = g_dt;
    const float B1 = (float)(16.0 / 135.0),  B3 = (float)(6656.0 / 12825.0);
    const float B4 = (float)(28561.0 / 56430.0), B5 = (float)(-9.0 / 50.0), B6 = (float)(2.0 / 55.0);
    const float C1 = (float)(25.0 / 216.0),  C3 = (float)(1408.0 / 2565.0);
    const float C4 = (float)(2197.0 / 4104.0), C5 = (float)(-1.0 / 5.0);

    float emax = 0.0f, smax = 0.0f;
    for (int i = blockIdx.x * blockDim.x + threadIdx.x; i < NV; i += gridDim.x * blockDim.x) {
        float4 x  = ((const float4*)g_X)[i];
        float4 k1 = ((const float4*)g_K[0])[i];
        float4 k3 = ((const float4*)g_K[2])[i];
        float4 k4 = ((const float4*)g_K[3])[i];
        float4 k5 = ((const float4*)g_K[4])[i];
        float4 k6 = ((const float4*)g_K[5])[i];
        float xx[4] = {x.x, x.y, x.z, x.w};
        float a1[4] = {k1.x, k1.y, k1.z, k1.w};
        float a3[4] = {k3.x, k3.y, k3.z, k3.w};
        float a4[4] = {k4.x, k4.y, k4.z, k4.w};
        float a5[4] = {k5.x, k5.y, k5.z, k5.w};
        float a6[4] = {k6.x, k6.y, k6.z, k6.w};
        float x5[4];
#pragma unroll
        for (int c = 0; c < 4; c++) {
            float s5 = B1 * a1[c] + B3 * a3[c] + B4 * a4[c] + B5 * a5[c] + B6 * a6[c];
            float s4 = C1 * a1[c] + C3 * a3[c] + C4 * a4[c] + C5 * a5[c];
            x5[c] = xx[c] + dt * s5;
            float x4v = xx[c] + dt * s4;
            emax = fmaxf(emax, fabsf(x5[c] - x4v));
            smax = fmaxf(smax, fabsf(x5[c] - xx[c]));
        }
        float4 o; o.x = x5[0]; o.y = x5[1]; o.z = x5[2]; o.w = x5[3];
        ((float4*)g_X5)[i] = o;
    }
#pragma unroll
    for (int o = 16; o > 0; o >>= 1) {
        emax = fmaxf(emax, __shfl_xor_sync(0xffffffffu, emax, o));
        smax = fmaxf(smax, __shfl_xor_sync(0xffffffffu, smax, o));
    }
    if ((threadIdx.x & 31) == 0) {
        atomicMax(&g_err_bits, __float_as_uint(emax));
        atomicMax(&g_spd_bits, __float_as_uint(smax));
    }
}

__global__ void k_decide() {
    if (g_done) { g_step = 0; return; }
    float err = __uint_as_float(g_err_bits);
    float spd = __uint_as_float(g_spd_bits);
    float dt = g_dt;
    int accept = (err < TOLC) ? 1 : 0;
    g_step = accept;
    if (accept && (spd / dt) < SPEED_TOL) g_done = 1;
    float scale = 0.9f * powf(TOLC / (err + 1e-12f), 0.2f);
    scale = fminf(fmaxf(scale, 0.1f), 4.0f);
    g_dt = fmaxf(dt * scale, MIN_DT);
    g_err_bits = 0u; g_spd_bits = 0u;
}

__global__ void k_update() {
    if (!g_step) return;
    for (int i = blockIdx.x * blockDim.x + threadIdx.x; i < NV; i += gridDim.x * blockDim.x)
        ((float4*)g_X)[i] = ((const float4*)g_X5)[i];
}

__global__ void k_final(float* __restrict__ out) {
    for (int i = blockIdx.x * blockDim.x + threadIdx.x; i < NV; i += gridDim.x * blockDim.x)
        ((float4*)out)[i] = ((const float4*)g_X)[i];
}

// ---------------- launch ----------------
extern "C" void kernel_launch(void* const* d_in, const int* in_sizes, int n_in,
                              void* d_out, int out_size) {
    const float* x0   = (const float*)d_in[0];
    const float* W    = (const float*)d_in[1];
    const float* bias = (const float*)d_in[2];
    float* out = (float*)d_out;

    cudaFuncSetAttribute(k_gemm_pvf, cudaFuncAttributeMaxDynamicSharedMemorySize, GEMM_SMEM);

    const int EW_GRID = 512, EW_BLK = 256;
    dim3 ggrid(DD / BNT, BD / BMT);  // (32, 4) = 128 CTAs

    k_splitW<<<EW_GRID, EW_BLK>>>(W);
    k_init<<<EW_GRID, EW_BLK>>>(x0);

    for (int step = 0; step < MAX_STEPS; step++) {
        k_stage<0><<<EW_GRID, EW_BLK>>>(0.f, 0.f, 0.f, 0.f, 0.f);
        k_gemm_pvf<<<ggrid, 256, GEMM_SMEM>>>(bias, 0);

        k_stage<1><<<EW_GRID, EW_BLK>>>(0.25f, 0.f, 0.f, 0.f, 0.f);
        k_gemm_pvf<<<ggrid, 256, GEMM_SMEM>>>(bias, 1);

        k_stage<2><<<EW_GRID, EW_BLK>>>((float)(3.0 / 32.0), (float)(9.0 / 32.0), 0.f, 0.f, 0.f);
        k_gemm_pvf<<<ggrid, 256, GEMM_SMEM>>>(bias, 2);

        k_stage<3><<<EW_GRID, EW_BLK>>>((float)(1932.0 / 2197.0), (float)(-7200.0 / 2197.0),
                                        (float)(7296.0 / 2197.0), 0.f, 0.f);
        k_gemm_pvf<<<ggrid, 256, GEMM_SMEM>>>(bias, 3);

        k_stage<4><<<EW_GRID, EW_BLK>>>((float)(439.0 / 216.0), -8.0f, (float)(3680.0 / 513.0),
                                        (float)(-845.0 / 4104.0), 0.f);
        k_gemm_pvf<<<ggrid, 256, GEMM_SMEM>>>(bias, 4);

        k_stage<5><<<EW_GRID, EW_BLK>>>((float)(-8.0 / 27.0), 2.0f, (float)(-3544.0 / 2565.0),
                                        (float)(1859.0 / 4104.0), (float)(-11.0 / 40.0));
        k_gemm_pvf<<<ggrid, 256, GEMM_SMEM>>>(bias, 5);

        k_combine<<<EW_GRID, EW_BLK>>>();
        k_decide<<<1, 1>>>();
        k_update<<<EW_GRID, EW_BLK>>>();
    }

    k_final<<<EW_GRID, EW_BLK>>>(out);
}

// round 4
// speedup vs baseline: 2.9177x; 1.2556x over previous
#include <cuda_runtime.h>
#include <cuda_bf16.h>
#include <cstdint>
#include <math.h>

// ---------------- problem sizes ----------------
#define BD   512
#define DD   2048
#define NTOT (BD*DD)
#define NV   (NTOT/4)
#define WTOT (DD*DD)
#define WV   (WTOT/4)

#define MAX_STEPS 32
#define TOLC      0.01f
#define SPEED_TOL 1e-3f
#define DT0       0.1f
#define MIN_DT    0.1f

// ---------------- device state ----------------
__device__ float g_X [NTOT];   // buffer 0
__device__ float g_X5[NTOT];   // buffer 1
__device__ float g_XS[NTOT];
__device__ __nv_bfloat16 g_Ah[NTOT];
__device__ __nv_bfloat16 g_Al[NTOT];
__device__ __nv_bfloat16 g_Wh[WTOT];
__device__ __nv_bfloat16 g_Wl[WTOT];
__device__ float g_K [6][NTOT];
__device__ float g_dt;
__device__ int   g_done;
__device__ int   g_cur;        // 0: g_X is current, 1: g_X5 is current
__device__ unsigned int g_err_bits;
__device__ unsigned int g_spd_bits;

// ---------------- helpers ----------------
__device__ __forceinline__ float reflect_f(float x) {
    int i = (int)x;
    return ((i & 1) == 0) ? x : 1.0f - x;
}
__device__ __forceinline__ void axpy4(float4& x, float c, const float4 k) {
    x.x += c * k.x; x.y += c * k.y; x.z += c * k.z; x.w += c * k.w;
}
__device__ __forceinline__ uint32_t smem_u32(const void* p) {
    uint32_t a;
    asm("{ .reg .u64 t; cvta.to.shared.u64 t, %1; cvt.u32.u64 %0, t; }" : "=r"(a) : "l"(p));
    return a;
}
__device__ __forceinline__ void cp16(uint32_t dst, const void* src) {
    asm volatile("cp.async.cg.shared.global [%0], [%1], 16;" :: "r"(dst), "l"(src));
}
__device__ __forceinline__ void cp_commit() { asm volatile("cp.async.commit_group;" ::: "memory"); }
template <int N> __device__ __forceinline__ void cp_wait() {
    asm volatile("cp.async.wait_group %0;" :: "n"(N) : "memory");
}
__device__ __forceinline__ void ldsm4(uint32_t* r, uint32_t addr) {
    asm volatile("ldmatrix.sync.aligned.m8n8.x4.shared.b16 {%0,%1,%2,%3}, [%4];"
                 : "=r"(r[0]), "=r"(r[1]), "=r"(r[2]), "=r"(r[3]) : "r"(addr));
}
__device__ __forceinline__ void mma16816(float* c, const uint32_t* a, const uint32_t* b) {
    asm("mma.sync.aligned.m16n8k16.row.col.f32.bf16.bf16.f32 "
        "{%0,%1,%2,%3}, {%4,%5,%6,%7}, {%8,%9}, {%0,%1,%2,%3};"
        : "+f"(c[0]), "+f"(c[1]), "+f"(c[2]), "+f"(c[3])
        : "r"(a[0]), "r"(a[1]), "r"(a[2]), "r"(a[3]), "r"(b[0]), "r"(b[1]));
}

// ---------------- init / split ----------------
__global__ void k_splitW(const float* __restrict__ W) {
    for (int i = blockIdx.x * blockDim.x + threadIdx.x; i < WV; i += gridDim.x * blockDim.x) {
        float4 w = ((const float4*)W)[i];
        __nv_bfloat16 h[4], l[4];
        float v[4] = {w.x, w.y, w.z, w.w};
#pragma unroll
        for (int c = 0; c < 4; c++) {
            h[c] = __float2bfloat16_rn(v[c]);
            l[c] = __float2bfloat16_rn(v[c] - __bfloat162float(h[c]));
        }
        *(uint2*)&g_Wh[i * 4] = *(uint2*)h;
        *(uint2*)&g_Wl[i * 4] = *(uint2*)l;
    }
}

__global__ void k_init(const float* __restrict__ x0) {
    for (int i = blockIdx.x * blockDim.x + threadIdx.x; i < NV; i += gridDim.x * blockDim.x)
        ((float4*)g_X)[i] = ((const float4*)x0)[i];
    if (blockIdx.x == 0 && threadIdx.x == 0) {
        g_dt = DT0; g_done = 0; g_cur = 0; g_err_bits = 0u; g_spd_bits = 0u;
    }
}

// ---------------- stage prep: XS = cur + dt*sum a_i K_i ; split r(XS) to bf16 ----------------
template <int NK>
__global__ void k_stage(float a0, float a1, float a2, float a3, float a4) {
    if (g_done) return;
    float dt = g_dt;
    const float4* X4 = (const float4*)(g_cur ? g_X5 : g_X);
    for (int i = blockIdx.x * blockDim.x + threadIdx.x; i < NV; i += gridDim.x * blockDim.x) {
        float4 xs = X4[i];
        if (NK >= 1) axpy4(xs, dt * a0, ((const float4*)g_K[0])[i]);
        if (NK >= 2) axpy4(xs, dt * a1, ((const float4*)g_K[1])[i]);
        if (NK >= 3) axpy4(xs, dt * a2, ((const float4*)g_K[2])[i]);
        if (NK >= 4) axpy4(xs, dt * a3, ((const float4*)g_K[3])[i]);
        if (NK >= 5) axpy4(xs, dt * a4, ((const float4*)g_K[4])[i]);
        float v[4] = {xs.x, xs.y, xs.z, xs.w};
        __nv_bfloat16 h[4], l[4];
#pragma unroll
        for (int c = 0; c < 4; c++) {
            float y = reflect_f(v[c]);
            h[c] = __float2bfloat16_rn(y);
            l[c] = __float2bfloat16_rn(y - __bfloat162float(h[c]));
        }
        ((float4*)g_XS)[i] = xs;
        *(uint2*)&g_Ah[i * 4] = *(uint2*)h;
        *(uint2*)&g_Al[i * 4] = *(uint2*)l;
    }
}

// ---------------- mma.sync GEMM: K[kidx] = sign(XS) * (r(XS) @ W + b) ----------------
// bf16x3. Tile 128x64x64, 512 threads (16 warps, warp tile 16x32), 4-stage cp.async.
#define BMT 128
#define BNT 64
#define BKC 64
#define NITER (DD / BKC)       // 32
#define PITCH 144              // 128B data + 16B pad
#define AH_OFF 0
#define AL_OFF (128 * PITCH)                   // 18432
#define BH_OFF (2 * 128 * PITCH)               // 36864
#define BL_OFF (2 * 128 * PITCH + 64 * PITCH)  // 46080
#define STAGE  (2 * 128 * PITCH + 2 * 64 * PITCH)  // 55296
#define GEMM_SMEM (4 * STAGE)  // 221184

__device__ __forceinline__ void load_stage(uint32_t sbase, int k0, int bm, int bn, int tid) {
#pragma unroll
    for (int i = 0; i < 2; i++) {
        int ch = tid + i * 512;          // 1024 chunks: 128 rows x 8
        int r = ch >> 3, c = ch & 7;
        uint32_t off = (uint32_t)(r * PITCH + c * 16);
        size_t go = (size_t)(bm + r) * DD + k0 + c * 8;
        cp16(sbase + AH_OFF + off, g_Ah + go);
        cp16(sbase + AL_OFF + off, g_Al + go);
    }
    {
        int r = tid >> 3, c = tid & 7;   // 512 chunks: 64 rows x 8
        uint32_t off = (uint32_t)(r * PITCH + c * 16);
        size_t go = (size_t)(bn + r) * DD + k0 + c * 8;
        cp16(sbase + BH_OFF + off, g_Wh + go);
        cp16(sbase + BL_OFF + off, g_Wl + go);
    }
    cp_commit();
}

__global__ __launch_bounds__(512, 1)
void k_gemm_pvf(const float* __restrict__ bias, int kidx) {
    if (g_done) return;
    extern __shared__ char smem[];
    uint32_t sb = smem_u32(smem);
    const int tid  = threadIdx.x;
    const int wid  = tid >> 5;
    const int lane = tid & 31;
    const int wm   = wid >> 1;      // 0..7  -> m offset 16 each
    const int wn   = wid & 1;       // 0..1  -> n offset 32 each
    const int bm   = blockIdx.y * BMT;
    const int bn   = blockIdx.x * BNT;

    float acc[4][4];
#pragma unroll
    for (int j = 0; j < 4; j++)
#pragma unroll
        for (int c = 0; c < 4; c++) acc[j][c] = 0.0f;

    load_stage(sb + 0 * STAGE, 0 * BKC, bm, bn, tid);
    load_stage(sb + 1 * STAGE, 1 * BKC, bm, bn, tid);
    load_stage(sb + 2 * STAGE, 2 * BKC, bm, bn, tid);

    const int g  = lane >> 3;
    const int l7 = lane & 7;
    const uint32_t offA_base = (uint32_t)((wm * 16 + ((g & 1) << 3) + l7) * PITCH + (g >> 1) * 16);
    const uint32_t offB0 = (uint32_t)((wn * 32 + ((g >> 1) << 3) + l7) * PITCH + (g & 1) * 16);
    const uint32_t offB1 = offB0 + 16 * PITCH;

    for (int it = 0; it < NITER; ++it) {
        if (it < NITER - 2)       cp_wait<2>();
        else if (it == NITER - 2) cp_wait<1>();
        else                      cp_wait<0>();
        __syncthreads();

        uint32_t stg = sb + (uint32_t)((it & 3) * STAGE);
#pragma unroll
        for (int ks = 0; ks < 4; ks++) {
            uint32_t ah[4], al[4], bh[2][4], bl[2][4];
            uint32_t koff = (uint32_t)(ks * 32);
            ldsm4(ah, stg + AH_OFF + offA_base + koff);
            ldsm4(al, stg + AL_OFF + offA_base + koff);
            ldsm4(bh[0], stg + BH_OFF + offB0 + koff);
            ldsm4(bl[0], stg + BL_OFF + offB0 + koff);
            ldsm4(bh[1], stg + BH_OFF + offB1 + koff);
            ldsm4(bl[1], stg + BL_OFF + offB1 + koff);
#pragma unroll
            for (int nt = 0; nt < 4; nt++) {
                const uint32_t* bhp = &bh[nt >> 1][(nt & 1) * 2];
                const uint32_t* blp = &bl[nt >> 1][(nt & 1) * 2];
                mma16816(acc[nt], ah, bhp);
                mma16816(acc[nt], ah, blp);
                mma16816(acc[nt], al, bhp);
            }
        }

        int J = it + 3;
        if (J < NITER) load_stage(sb + (uint32_t)((J & 3) * STAGE), J * BKC, bm, bn, tid);
    }

    // epilogue
    float* Kout = g_K[kidx];
    const int m0 = bm + wm * 16 + (lane >> 2);
    const int n_base = bn + wn * 32;
#pragma unroll
    for (int nt = 0; nt < 4; nt++) {
        int n0 = n_base + nt * 8 + 2 * (lane & 3);
        float2 bv = *(const float2*)&bias[n0];
#pragma unroll
        for (int half = 0; half < 2; half++) {
            int m = m0 + half * 8;
            float2 xs = *(const float2*)&g_XS[(size_t)m * DD + n0];
            float v0 = acc[nt][half * 2 + 0] + bv.x;
            float v1 = acc[nt][half * 2 + 1] + bv.y;
            float2 o;
            o.x = (((int)xs.x & 1) == 0) ? v0 : -v0;
            o.y = (((int)xs.y & 1) == 0) ? v1 : -v1;
            *(float2*)&Kout[(size_t)m * DD + n0] = o;
        }
    }
}

// ---------------- combine: alt = cur + dt*sum; err/speed reduction ----------------
__global__ void k_combine() {
    if (g_done) return;
    const float dt = g_dt;
    const float B1 = (float)(16.0 / 135.0),  B3 = (float)(6656.0 / 12825.0);
    const float B4 = (float)(28561.0 / 56430.0), B5 = (float)(-9.0 / 50.0), B6 = (float)(2.0 / 55.0);
    const float C1 = (float)(25.0 / 216.0),  C3 = (float)(1408.0 / 2565.0);
    const float C4 = (float)(2197.0 / 4104.0), C5 = (float)(-1.0 / 5.0);

    const float4* SRC = (const float4*)(g_cur ? g_X5 : g_X);
    float4*       DST = (float4*)(g_cur ? g_X : g_X5);

    float emax = 0.0f, smax = 0.0f;
    for (int i = blockIdx.x * blockDim.x + threadIdx.x; i < NV; i += gridDim.x * blockDim.x) {
        float4 x  = SRC[i];
        float4 k1 = ((const float4*)g_K[0])[i];
        float4 k3 = ((const float4*)g_K[2])[i];
        float4 k4 = ((const float4*)g_K[3])[i];
        float4 k5 = ((const float4*)g_K[4])[i];
        float4 k6 = ((const float4*)g_K[5])[i];
        float xx[4] = {x.x, x.y, x.z, x.w};
        float a1[4] = {k1.x, k1.y, k1.z, k1.w};
        float a3[4] = {k3.x, k3.y, k3.z, k3.w};
        float a4[4] = {k4.x, k4.y, k4.z, k4.w};
        float a5[4] = {k5.x, k5.y, k5.z, k5.w};
        float a6[4] = {k6.x, k6.y, k6.z, k6.w};
        float x5[4];
#pragma unroll
        for (int c = 0; c < 4; c++) {
            float s5 = B1 * a1[c] + B3 * a3[c] + B4 * a4[c] + B5 * a5[c] + B6 * a6[c];
            float s4 = C1 * a1[c] + C3 * a3[c] + C4 * a4[c] + C5 * a5[c];
            x5[c] = xx[c] + dt * s5;
            float x4v = xx[c] + dt * s4;
            emax = fmaxf(emax, fabsf(x5[c] - x4v));
            smax = fmaxf(smax, fabsf(x5[c] - xx[c]));
        }
        float4 o; o.x = x5[0]; o.y = x5[1]; o.z = x5[2]; o.w = x5[3];
        DST[i] = o;
    }
#pragma unroll
    for (int o = 16; o > 0; o >>= 1) {
        emax = fmaxf(emax, __shfl_xor_sync(0xffffffffu, emax, o));
        smax = fmaxf(smax, __shfl_xor_sync(0xffffffffu, smax, o));
    }
    if ((threadIdx.x & 31) == 0) {
        atomicMax(&g_err_bits, __float_as_uint(emax));
        atomicMax(&g_spd_bits, __float_as_uint(smax));
    }
}

// ---------------- controller (1 thread) ----------------
__global__ void k_decide() {
    if (g_done) return;
    float err = __uint_as_float(g_err_bits);
    float spd = __uint_as_float(g_spd_bits);
    float dt = g_dt;
    int accept = (err < TOLC) ? 1 : 0;
    if (accept) {
        g_cur ^= 1;                      // candidate becomes current
        if ((spd / dt) < SPEED_TOL) g_done = 1;
    }
    float scale = 0.9f * powf(TOLC / (err + 1e-12f), 0.2f);
    scale = fminf(fmaxf(scale, 0.1f), 4.0f);
    g_dt = fmaxf(dt * scale, MIN_DT);
    g_err_bits = 0u; g_spd_bits = 0u;
}

// ---------------- output ----------------
__global__ void k_final(float* __restrict__ out) {
    const float4* SRC = (const float4*)(g_cur ? g_X5 : g_X);
    for (int i = blockIdx.x * blockDim.x + threadIdx.x; i < NV; i += gridDim.x * blockDim.x)
        ((float4*)out)[i] = SRC[i];
}

// ---------------- launch ----------------
extern "C" void kernel_launch(void* const* d_in, const int* in_sizes, int n_in,
                              void* d_out, int out_size) {
    const float* x0   = (const float*)d_in[0];
    const float* W    = (const float*)d_in[1];
    const float* bias = (const float*)d_in[2];
    float* out = (float*)d_out;

    cudaFuncSetAttribute(k_gemm_pvf, cudaFuncAttributeMaxDynamicSharedMemorySize, GEMM_SMEM);

    const int EW_GRID = 512, EW_BLK = 256;
    dim3 ggrid(DD / BNT, BD / BMT);  // (32, 4) = 128 CTAs

    k_splitW<<<EW_GRID, EW_BLK>>>(W);
    k_init<<<EW_GRID, EW_BLK>>>(x0);

    for (int step = 0; step < MAX_STEPS; step++) {
        k_stage<0><<<EW_GRID, EW_BLK>>>(0.f, 0.f, 0.f, 0.f, 0.f);
        k_gemm_pvf<<<ggrid, 512, GEMM_SMEM>>>(bias, 0);

        k_stage<1><<<EW_GRID, EW_BLK>>>(0.25f, 0.f, 0.f, 0.f, 0.f);
        k_gemm_pvf<<<ggrid, 512, GEMM_SMEM>>>(bias, 1);

        k_stage<2><<<EW_GRID, EW_BLK>>>((float)(3.0 / 32.0), (float)(9.0 / 32.0), 0.f, 0.f, 0.f);
        k_gemm_pvf<<<ggrid, 512, GEMM_SMEM>>>(bias, 2);

        k_stage<3><<<EW_GRID, EW_BLK>>>((float)(1932.0 / 2197.0), (float)(-7200.0 / 2197.0),
                                        (float)(7296.0 / 2197.0), 0.f, 0.f);
        k_gemm_pvf<<<ggrid, 512, GEMM_SMEM>>>(bias, 3);

        k_stage<4><<<EW_GRID, EW_BLK>>>((float)(439.0 / 216.0), -8.0f, (float)(3680.0 / 513.0),
                                        (float)(-845.0 / 4104.0), 0.f);
        k_gemm_pvf<<<ggrid, 512, GEMM_SMEM>>>(bias, 4);

        k_stage<5><<<EW_GRID, EW_BLK>>>((float)(-8.0 / 27.0), 2.0f, (float)(-3544.0 / 2565.0),
                                        (float)(1859.0 / 4104.0), (float)(-11.0 / 40.0));
        k_gemm_pvf<<<ggrid, 512, GEMM_SMEM>>>(bias, 5);

        k_combine<<<EW_GRID, EW_BLK>>>();
        k_decide<<<1, 1>>>();
    }

    k_final<<<EW_GRID, EW_BLK>>>(out);
}